// round 6
// baseline (speedup 1.0000x reference)
#include <cuda_runtime.h>
#include <cstdint>

// Problem constants (fixed by the reference)
#define N_TOKENS  131072
#define HIDDEN    2048
#define N_RANKS   8
#define N_EXPERTS 16
#define NSEG (N_RANKS * N_EXPERTS)   // 128
#define VEC_PER_ROW (HIDDEN / 4)     // 512 float4

// Scratch (no cudaMalloc allowed)
__device__ int g_src_row[N_TOKENS];   // source row for each output row

// d_out float layout:
//   [0, N_TOKENS*HIDDEN)   permute_tokens
//   [+N_TOKENS)            permute_per_token_scales
//   [+N_TOKENS)            idx (as float, exact: < 2^24)
//   [+N_EXPERTS)           expert_token_num (as float)
#define OFF_SCALES ((size_t)N_TOKENS * HIDDEN)
#define OFF_IDX    (OFF_SCALES + N_TOKENS)
#define OFF_ETN    (OFF_IDX + N_TOKENS)

// ---------------------------------------------------------------------------
// Kernel 1: fused setup + index. 512 blocks x 256 threads; each thread owns
// exactly one token. Each block rebuilds the two 128-entry prefix tables with
// a 7-step Hillis-Steele scan.
// ---------------------------------------------------------------------------
__global__ void __launch_bounds__(256)
k_index(const int* __restrict__ counts, const float* __restrict__ scales,
        float* __restrict__ out) {
    __shared__ int sa[NSEG];          // inclusive scan, input order  (r*E + e)
    __shared__ int sb[NSEG];          // inclusive scan, output order (e*R + r)
    __shared__ int s_in_start[NSEG];
    __shared__ int s_out_start[NSEG + 1];

    const int t = threadIdx.x;

    int own_a = 0, own_b = 0;
    if (t < NSEG) {
        own_a = __ldg(&counts[t]);                                    // flat r*E+e
        own_b = __ldg(&counts[(t & 7) * N_EXPERTS + (t >> 3)]);       // seg e*R+r
        sa[t] = own_a;
        sb[t] = own_b;
    }
    __syncthreads();

    // Hillis-Steele inclusive scan over both tables, 7 steps.
    #pragma unroll
    for (int off = 1; off < NSEG; off <<= 1) {
        int va = 0, vb = 0;
        if (t < NSEG && t >= off) { va = sa[t - off]; vb = sb[t - off]; }
        __syncthreads();
        if (t < NSEG && t >= off) { sa[t] += va; sb[t] += vb; }
        __syncthreads();
    }

    if (t < NSEG) {
        s_in_start[t]  = sa[t] - own_a;   // exclusive
        s_out_start[t] = sb[t] - own_b;
    }
    if (t == 0) s_out_start[NSEG] = N_TOKENS;

    // expert_token_num[e] = sum_r counts[r][e]  (block 0 only)
    if (blockIdx.x == 0 && t < N_EXPERTS) {
        int sum = 0;
        #pragma unroll
        for (int r = 0; r < N_RANKS; ++r) sum += __ldg(&counts[r * N_EXPERTS + t]);
        out[OFF_ETN + t] = (float)sum;
    }
    __syncthreads();

    const int i = blockIdx.x * 256 + t;   // one token per thread, grid = 512

    // binary search: largest s with out_start[s] <= i  (7 steps)
    int lo = 0, hi = NSEG;
    #pragma unroll 7
    while (hi - lo > 1) {
        int mid = (lo + hi) >> 1;
        if (s_out_start[mid] <= i) lo = mid; else hi = mid;
    }
    const int e = lo >> 3;                // lo / N_RANKS
    const int r = lo & 7;                 // lo % N_RANKS
    const int src = s_in_start[r * N_EXPERTS + e] + (i - s_out_start[lo]);

    g_src_row[i]        = src;
    out[OFF_SCALES + i] = __ldg(&scales[src]);
    out[OFF_IDX + i]    = (float)src;
}

// ---------------------------------------------------------------------------
// Kernel 2: the big gather copy. TWO rows per block, 256 threads.
// 4 independent front-batched LDG.128 per thread (2 per row), then 4 STG.
// 16 KB per block, blocks = 65536. No loops, no serial dependencies.
// ---------------------------------------------------------------------------
__global__ void __launch_bounds__(256, 8) k_copy(const float4* __restrict__ tokens,
                                                 float4* __restrict__ out) {
    const int row0 = blockIdx.x * 2;
    const int t = threadIdx.x;

    const int src0 = __ldg(&g_src_row[row0]);       // broadcast
    const int src1 = __ldg(&g_src_row[row0 + 1]);   // broadcast

    const float4* __restrict__ in0 = tokens + (size_t)src0 * VEC_PER_ROW;
    const float4* __restrict__ in1 = tokens + (size_t)src1 * VEC_PER_ROW;
    float4* __restrict__ o0 = out + (size_t)row0 * VEC_PER_ROW;
    float4* __restrict__ o1 = o0 + VEC_PER_ROW;

    // 4 independent loads, front-batched for max MLP.
    float4 a = __ldg(&in0[t]);
    float4 b = __ldg(&in0[t + 256]);
    float4 c = __ldg(&in1[t]);
    float4 d = __ldg(&in1[t + 256]);

    o0[t]       = a;
    o0[t + 256] = b;
    o1[t]       = c;
    o1[t + 256] = d;
}

// ---------------------------------------------------------------------------
extern "C" void kernel_launch(void* const* d_in, const int* in_sizes, int n_in,
                              void* d_out, int out_size) {
    const float* tokens = (const float*)d_in[0];
    const int*   counts = (const int*)d_in[1];     // [N_RANKS, N_EXPERTS]
    const float* scales = (const float*)d_in[2];
    // d_in[3] = expert_token_num_type (1), d_in[4] = idx_type (0) — fixed.
    float* out = (float*)d_out;

    k_index<<<N_TOKENS / 256, 256>>>(counts, scales, out);
    k_copy<<<N_TOKENS / 2, 256>>>((const float4*)tokens, (float4*)out);
}

// round 7
// speedup vs baseline: 1.0041x; 1.0041x over previous
#include <cuda_runtime.h>
#include <cstdint>

// Problem constants (fixed by the reference)
#define N_TOKENS  131072
#define HIDDEN    2048
#define N_RANKS   8
#define N_EXPERTS 16
#define NSEG (N_RANKS * N_EXPERTS)   // 128
#define VEC_PER_ROW (HIDDEN / 4)     // 512 float4

// d_out float layout:
//   [0, N_TOKENS*HIDDEN)   permute_tokens
//   [+N_TOKENS)            permute_per_token_scales
//   [+N_TOKENS)            idx (as float, exact: < 2^24)
//   [+N_EXPERTS)           expert_token_num (as float)
#define OFF_SCALES ((size_t)N_TOKENS * HIDDEN)
#define OFF_IDX    (OFF_SCALES + N_TOKENS)
#define OFF_ETN    (OFF_IDX + N_TOKENS)

// ---------------------------------------------------------------------------
// Single fused one-shot kernel: 65536 blocks x 256 threads, 2 rows per block.
// Per-block prologue: parallel 128-entry scan (Hillis-Steele, 7 steps) to
// rebuild the segment tables, then every thread redundantly binary-searches
// both of the block's rows (smem broadcast, no extra sync). Then the proven
// front-batched 4x LDG.128 / 4x STG.128 row copy. Scale/idx written inline.
// ---------------------------------------------------------------------------
__global__ void __launch_bounds__(256, 8)
k_fused(const float4* __restrict__ tokens,
        const int*    __restrict__ counts,
        const float*  __restrict__ scales,
        float*        __restrict__ out) {
    __shared__ int sa[NSEG];            // inclusive scan, input order  (r*E + e)
    __shared__ int sb[NSEG];            // inclusive scan, output order (e*R + r)
    __shared__ int s_in_start[NSEG];
    __shared__ int s_out_start[NSEG + 1];

    const int t = threadIdx.x;
    float4* __restrict__ out4 = (float4*)out;

    int own_a = 0, own_b = 0;
    if (t < NSEG) {
        own_a = __ldg(&counts[t]);                                 // flat r*E+e
        own_b = __ldg(&counts[(t & 7) * N_EXPERTS + (t >> 3)]);    // seg e*R+r
        sa[t] = own_a;
        sb[t] = own_b;
    }
    __syncthreads();

    // Hillis-Steele inclusive scan over both tables, 7 steps.
    #pragma unroll
    for (int off = 1; off < NSEG; off <<= 1) {
        int va = 0, vb = 0;
        if (t < NSEG && t >= off) { va = sa[t - off]; vb = sb[t - off]; }
        __syncthreads();
        if (t < NSEG && t >= off) { sa[t] += va; sb[t] += vb; }
        __syncthreads();
    }

    if (t < NSEG) {
        s_in_start[t]  = sa[t] - own_a;   // exclusive
        s_out_start[t] = sb[t] - own_b;
    }
    if (t == 0) s_out_start[NSEG] = N_TOKENS;

    // expert_token_num[e] = sum_r counts[r][e]  (block 0 only)
    if (blockIdx.x == 0 && t < N_EXPERTS) {
        int sum = 0;
        #pragma unroll
        for (int r = 0; r < N_RANKS; ++r) sum += __ldg(&counts[r * N_EXPERTS + t]);
        out[OFF_ETN + t] = (float)sum;
    }
    __syncthreads();

    const int row0 = blockIdx.x * 2;

    // Every thread searches both rows redundantly (pure smem broadcast reads).
    int src[2];
    #pragma unroll
    for (int k = 0; k < 2; ++k) {
        const int row = row0 + k;
        int lo = 0, hi = NSEG;
        #pragma unroll 7
        while (hi - lo > 1) {
            int mid = (lo + hi) >> 1;
            if (s_out_start[mid] <= row) lo = mid; else hi = mid;
        }
        const int e = lo >> 3;            // lo / N_RANKS
        const int r = lo & 7;             // lo % N_RANKS
        src[k] = s_in_start[r * N_EXPERTS + e] + (row - s_out_start[lo]);
    }

    const float4* __restrict__ in0 = tokens + (size_t)src[0] * VEC_PER_ROW;
    const float4* __restrict__ in1 = tokens + (size_t)src[1] * VEC_PER_ROW;
    float4* __restrict__ o0 = out4 + (size_t)row0 * VEC_PER_ROW;
    float4* __restrict__ o1 = o0 + VEC_PER_ROW;

    // 4 independent front-batched loads.
    float4 a = __ldg(&in0[t]);
    float4 b = __ldg(&in0[t + 256]);
    float4 c = __ldg(&in1[t]);
    float4 d = __ldg(&in1[t + 256]);

    // Scale + idx inline (threads 0/1, one row each).
    if (t < 2) {
        const int row = row0 + t;
        const int s   = src[t];
        out[OFF_SCALES + row] = __ldg(&scales[s]);
        out[OFF_IDX + row]    = (float)s;
    }

    o0[t]       = a;
    o0[t + 256] = b;
    o1[t]       = c;
    o1[t + 256] = d;
}

// ---------------------------------------------------------------------------
extern "C" void kernel_launch(void* const* d_in, const int* in_sizes, int n_in,
                              void* d_out, int out_size) {
    const float* tokens = (const float*)d_in[0];
    const int*   counts = (const int*)d_in[1];     // [N_RANKS, N_EXPERTS]
    const float* scales = (const float*)d_in[2];
    // d_in[3] = expert_token_num_type (1), d_in[4] = idx_type (0) — fixed.
    float* out = (float*)d_out;

    k_fused<<<N_TOKENS / 2, 256>>>((const float4*)tokens, counts, scales, out);
}

// round 8
// speedup vs baseline: 1.0125x; 1.0083x over previous
#include <cuda_runtime.h>
#include <cstdint>

// Problem constants (fixed by the reference)
#define N_TOKENS  131072
#define HIDDEN    2048
#define N_RANKS   8
#define N_EXPERTS 16
#define NSEG (N_RANKS * N_EXPERTS)   // 128
#define VEC_PER_ROW (HIDDEN / 4)     // 512 float4

// d_out float layout:
//   [0, N_TOKENS*HIDDEN)   permute_tokens
//   [+N_TOKENS)            permute_per_token_scales
//   [+N_TOKENS)            idx (as float, exact: < 2^24)
//   [+N_EXPERTS)           expert_token_num (as float)
#define OFF_SCALES ((size_t)N_TOKENS * HIDDEN)
#define OFF_IDX    (OFF_SCALES + N_TOKENS)
#define OFF_ETN    (OFF_IDX + N_TOKENS)

__device__ __forceinline__ int warp_exscan(int v, int lane) {
    int inc = v;
    #pragma unroll
    for (int o = 1; o < 32; o <<= 1) {
        int n = __shfl_up_sync(0xffffffffu, inc, o);
        if (lane >= o) inc += n;
    }
    return inc - v;   // exclusive
}

// ---------------------------------------------------------------------------
// Single fused one-shot kernel: 65536 blocks x 256 threads, 2 rows per block.
// Prologue: warp 0 builds both 128-entry exclusive-prefix tables via a
// register scan (4 entries/lane + shfl exscan) — ONE __syncthreads total.
// Then: redundant 7-step smem binary search per thread, front-batched
// 4x LDG.128 / 4x STG.128 two-row copy, scale/idx inline.
// ---------------------------------------------------------------------------
__global__ void __launch_bounds__(256, 8)
k_fused(const float4* __restrict__ tokens,
        const int*    __restrict__ counts,
        const float*  __restrict__ scales,
        float*        __restrict__ out) {
    __shared__ int s_in_start[NSEG];
    __shared__ int s_out_start[NSEG + 1];

    const int t = threadIdx.x;
    float4* __restrict__ out4 = (float4*)out;

    if (t < 32) {
        const int base = t * 4;
        // table A: input order (flat r*E+e) — contiguous, one LDG.128
        const int4 av = __ldg((const int4*)(counts + base));
        // table B: output order s = e*R+r  ->  count index (s&7)*E + (s>>3)
        const int b0 = __ldg(&counts[((base + 0) & 7) * N_EXPERTS + ((base + 0) >> 3)]);
        const int b1 = __ldg(&counts[((base + 1) & 7) * N_EXPERTS + ((base + 1) >> 3)]);
        const int b2 = __ldg(&counts[((base + 2) & 7) * N_EXPERTS + ((base + 2) >> 3)]);
        const int b3 = __ldg(&counts[((base + 3) & 7) * N_EXPERTS + ((base + 3) >> 3)]);

        const int sumA = av.x + av.y + av.z + av.w;
        const int sumB = b0 + b1 + b2 + b3;
        int exA = warp_exscan(sumA, t);
        int exB = warp_exscan(sumB, t);

        s_in_start[base + 0] = exA;
        s_in_start[base + 1] = exA + av.x;
        s_in_start[base + 2] = exA + av.x + av.y;
        s_in_start[base + 3] = exA + av.x + av.y + av.z;

        s_out_start[base + 0] = exB;
        s_out_start[base + 1] = exB + b0;
        s_out_start[base + 2] = exB + b0 + b1;
        s_out_start[base + 3] = exB + b0 + b1 + b2;
        if (t == 31) s_out_start[NSEG] = N_TOKENS;
    }
    // expert_token_num (block 0, warp 1 — overlaps warp 0's scan)
    if (blockIdx.x == 0 && t >= 32 && t < 32 + N_EXPERTS) {
        const int e = t - 32;
        int sum = 0;
        #pragma unroll
        for (int r = 0; r < N_RANKS; ++r) sum += __ldg(&counts[r * N_EXPERTS + e]);
        out[OFF_ETN + e] = (float)sum;
    }
    __syncthreads();   // the ONLY barrier

    const int row0 = blockIdx.x * 2;

    // Every thread searches both rows redundantly (smem broadcast reads).
    int src[2];
    #pragma unroll
    for (int k = 0; k < 2; ++k) {
        const int row = row0 + k;
        int lo = 0, hi = NSEG;
        #pragma unroll 7
        while (hi - lo > 1) {
            int mid = (lo + hi) >> 1;
            if (s_out_start[mid] <= row) lo = mid; else hi = mid;
        }
        const int e = lo >> 3;            // lo / N_RANKS
        const int r = lo & 7;             // lo % N_RANKS
        src[k] = s_in_start[r * N_EXPERTS + e] + (row - s_out_start[lo]);
    }

    const float4* __restrict__ in0 = tokens + (size_t)src[0] * VEC_PER_ROW;
    const float4* __restrict__ in1 = tokens + (size_t)src[1] * VEC_PER_ROW;
    float4* __restrict__ o0 = out4 + (size_t)row0 * VEC_PER_ROW;
    float4* __restrict__ o1 = o0 + VEC_PER_ROW;

    // 4 independent front-batched loads.
    float4 a = __ldg(&in0[t]);
    float4 b = __ldg(&in0[t + 256]);
    float4 c = __ldg(&in1[t]);
    float4 d = __ldg(&in1[t + 256]);

    // Scale + idx inline (threads 0/1, one row each).
    if (t < 2) {
        const int row = row0 + t;
        const int s   = src[t];
        out[OFF_SCALES + row] = __ldg(&scales[s]);
        out[OFF_IDX + row]    = (float)s;
    }

    o0[t]       = a;
    o0[t + 256] = b;
    o1[t]       = c;
    o1[t + 256] = d;
}

// ---------------------------------------------------------------------------
extern "C" void kernel_launch(void* const* d_in, const int* in_sizes, int n_in,
                              void* d_out, int out_size) {
    const float* tokens = (const float*)d_in[0];
    const int*   counts = (const int*)d_in[1];     // [N_RANKS, N_EXPERTS]
    const float* scales = (const float*)d_in[2];
    // d_in[3] = expert_token_num_type (1), d_in[4] = idx_type (0) — fixed.
    float* out = (float*)d_out;

    k_fused<<<N_TOKENS / 2, 256>>>((const float4*)tokens, counts, scales, out);
}